// round 2
// baseline (speedup 1.0000x reference)
#include <cuda_runtime.h>
#include <cstdint>

// Problem: out[N,128] = [ self_x@Ws + bs , ((adj@nx)/deg)@Wn + bn ]
// N = K = 16384, D = 64. Dominant cost: adj (1 GiB) streamed once through a
// TF32 mma.sync GEMM with a fused ones-column for the row-degree.

#define Nn 16384
#define Kk 16384
#define BM 64
#define BK 16
#define NSTAGE 4
#define ASTR 20   // A smem stride (floats): conflict-free for m16n8k8 A frags
#define BSTR 88   // B smem stride (floats): conflict-free for B frags
#define BNT 9     // 9 n-tiles of 8 -> 72 cols (64 data + ones + pad)

__device__ float g_X2[Kk * 72];    // [K][72]: cols 0..63 = neighbor_x, 64 = 1, 65..71 = 0
__device__ float g_AGG[Nn * 64];   // (adj @ nx) / deg

__device__ __forceinline__ void cp16(float* s, const float* g) {
    uint32_t sa = (uint32_t)__cvta_generic_to_shared(s);
    asm volatile("cp.async.cg.shared.global [%0], [%1], 16;" :: "r"(sa), "l"(g));
}
__device__ __forceinline__ void cp_commit() { asm volatile("cp.async.commit_group;"); }
__device__ __forceinline__ void cp_wait2()  { asm volatile("cp.async.wait_group 2;"); }

// ---------------------------------------------------------------------------
// Kernel 1: build B matrix [K, 72] = [neighbor_x | ones | zeros]
// ---------------------------------------------------------------------------
__global__ void prep_x2(const float* __restrict__ nx) {
    int idx = blockIdx.x * 256 + threadIdx.x;
    if (idx >= Kk * 72) return;
    int k = idx / 72, c = idx % 72;
    float v = 0.f;
    if (c < 64)       v = nx[k * 64 + c];
    else if (c == 64) v = 1.f;
    g_X2[idx] = v;
}

// ---------------------------------------------------------------------------
// Kernel 2: C[16384, 72] = adj @ X2 via tf32 mma.sync, 4-stage cp.async pipe.
// Col 64 of C is deg; epilogue writes g_AGG = C[:,0:64] / max(deg,1).
// Block: 64 rows, 128 threads (4 warps, each warp 16 rows x 72 cols).
// ---------------------------------------------------------------------------
__global__ __launch_bounds__(128) void agg_gemm(const float* __restrict__ adj) {
    __shared__ float As[NSTAGE][BM * ASTR];   // 4 * 1280 floats
    __shared__ float Bs[NSTAGE][BK * BSTR];   // 4 * 1408 floats
    __shared__ float degs[BM];

    const int tid  = threadIdx.x;
    const int lane = tid & 31;
    const int warp = tid >> 5;
    const int wm   = warp * 16;
    const float* gA0 = adj + (size_t)blockIdx.x * BM * Kk;

    float c[BNT][4];
#pragma unroll
    for (int i = 0; i < BNT; i++) { c[i][0] = c[i][1] = c[i][2] = c[i][3] = 0.f; }

    auto load_stage = [&](int st, int kt) {
        const int k0 = kt * BK;
        const float* gA = gA0 + k0;
#pragma unroll
        for (int i = 0; i < 2; i++) {                 // A tile: 64 x 16 f32
            int id = tid + 128 * i;
            int m = id >> 2, kg = id & 3;
            cp16(&As[st][m * ASTR + kg * 4], gA + (size_t)m * Kk + kg * 4);
        }
        const float* gB = g_X2 + (size_t)k0 * 72;     // B tile: 16 x 72 f32
#pragma unroll
        for (int i = 0; i < 3; i++) {
            int id = tid + 128 * i;
            if (id < 288) {
                int kr = id / 18, cg = (id % 18) * 4;
                cp16(&Bs[st][kr * BSTR + cg], gB + kr * 72 + cg);
            }
        }
    };

    const int NKT = Kk / BK;  // 1024
    for (int s = 0; s < NSTAGE - 1; s++) { load_stage(s, s); cp_commit(); }

    for (int kt = 0; kt < NKT; kt++) {
        cp_wait2();
        __syncthreads();
        int nxt = kt + NSTAGE - 1;
        if (nxt < NKT) load_stage(nxt & 3, nxt);
        cp_commit();

        const float* A = As[kt & 3];
        const float* B = Bs[kt & 3];
#pragma unroll
        for (int ks = 0; ks < 2; ks++) {
            const int kk = ks * 8 + (lane & 3);
            const int m0 = wm + (lane >> 2);
            // tf32 inputs: fp32 regs, low mantissa bits ignored by HW (truncation;
            // random-sign cancellation over K keeps rel err ~1e-4).
            uint32_t a0 = __float_as_uint(A[m0 * ASTR + kk]);
            uint32_t a1 = __float_as_uint(A[(m0 + 8) * ASTR + kk]);
            uint32_t a2 = __float_as_uint(A[m0 * ASTR + kk + 4]);
            uint32_t a3 = __float_as_uint(A[(m0 + 8) * ASTR + kk + 4]);
            const int nb = lane >> 2;
#pragma unroll
            for (int nt = 0; nt < BNT; nt++) {
                uint32_t b0 = __float_as_uint(B[kk * BSTR + nt * 8 + nb]);
                uint32_t b1 = __float_as_uint(B[(kk + 4) * BSTR + nt * 8 + nb]);
                asm volatile(
                    "mma.sync.aligned.m16n8k8.row.col.f32.tf32.tf32.f32 "
                    "{%0,%1,%2,%3}, {%4,%5,%6,%7}, {%8,%9}, {%0,%1,%2,%3};"
                    : "+f"(c[nt][0]), "+f"(c[nt][1]), "+f"(c[nt][2]), "+f"(c[nt][3])
                    : "r"(a0), "r"(a1), "r"(a2), "r"(a3), "r"(b0), "r"(b1));
            }
        }
    }

    // Epilogue: deg = column 64 (n-tile 8, col offset 0 -> lanes with lane%4==0)
    if ((lane & 3) == 0) {
        degs[wm + (lane >> 2)]     = c[8][0];
        degs[wm + (lane >> 2) + 8] = c[8][2];
    }
    __syncthreads();

    const int r0 = blockIdx.x * BM + wm + (lane >> 2);
    const float inv0 = 1.f / fmaxf(degs[wm + (lane >> 2)],     1.f);
    const float inv1 = 1.f / fmaxf(degs[wm + (lane >> 2) + 8], 1.f);
#pragma unroll
    for (int nt = 0; nt < 8; nt++) {
        int col = nt * 8 + 2 * (lane & 3);
        g_AGG[(size_t)r0 * 64 + col]           = c[nt][0] * inv0;
        g_AGG[(size_t)r0 * 64 + col + 1]       = c[nt][1] * inv0;
        g_AGG[(size_t)(r0 + 8) * 64 + col]     = c[nt][2] * inv1;
        g_AGG[(size_t)(r0 + 8) * 64 + col + 1] = c[nt][3] * inv1;
    }
}

// ---------------------------------------------------------------------------
// Kernel 3: out[r, 0:64] = self_x[r] @ Ws + bs ; out[r, 64:128] = AGG[r] @ Wn + bn
// One warp per row; lanes 0..15 handle self half, 16..31 neighbor half.
// ---------------------------------------------------------------------------
__global__ __launch_bounds__(256) void finalize(
    const float* __restrict__ self_x, const float* __restrict__ Ws,
    const float* __restrict__ Wn, const float* __restrict__ bs,
    const float* __restrict__ bn, float* __restrict__ out)
{
    const int warp = threadIdx.x >> 5, lane = threadIdx.x & 31;
    const int r = blockIdx.x * 8 + warp;
    const bool selfside = lane < 16;
    const int c0 = selfside ? lane * 4 : (lane - 16) * 4;
    const float* src  = selfside ? (self_x + (size_t)r * 64) : (g_AGG + (size_t)r * 64);
    const float* W    = selfside ? Ws : Wn;
    const float* bias = selfside ? bs : bn;

    float4 acc = *(const float4*)(bias + c0);
#pragma unroll 8
    for (int k = 0; k < 64; k++) {
        float v = src[k];
        float4 w = *(const float4*)(W + k * 64 + c0);
        acc.x += v * w.x; acc.y += v * w.y; acc.z += v * w.z; acc.w += v * w.w;
    }
    *(float4*)(out + (size_t)r * 128 + lane * 4) = acc;
}

// ---------------------------------------------------------------------------
extern "C" void kernel_launch(void* const* d_in, const int* in_sizes, int n_in,
                              void* d_out, int out_size)
{
    const float* self_x     = (const float*)d_in[0];
    const float* neighbor_x = (const float*)d_in[1];
    const float* adj        = (const float*)d_in[2];
    const float* Ws         = (const float*)d_in[3];
    const float* Wn         = (const float*)d_in[4];
    const float* bs         = (const float*)d_in[5];
    const float* bn         = (const float*)d_in[6];
    float* out = (float*)d_out;

    prep_x2<<<(Kk * 72 + 255) / 256, 256>>>(neighbor_x);
    agg_gemm<<<Nn / BM, 128>>>(adj);
    finalize<<<Nn / 8, 256>>>(self_x, Ws, Wn, bs, bn, out);
}

// round 11
// speedup vs baseline: 1.4295x; 1.4295x over previous
#include <cuda_runtime.h>
#include <cuda_fp16.h>
#include <cstdint>

// out[N,128] = [ self_x@Ws + bs , ((adj@nx)/deg)@Wn + bn ]
// tcgen05 is unavailable (ptxas targets sm_103 without 'a' features), so the
// big GEMM C[16384,72] = adj @ [nx | 1 | 0] runs on fallback mma.sync using
// fp16 m16n8k16 (same 10-bit mantissa as tf32, 2x MACs/instruction).
// adj stays fp32 in DRAM; conversion to fp16 happens in-kernel in smem.

#define Nn 16384
#define Kk 16384
#define BM 64
#define KT 32
#define NKT (Kk / KT)      // 512
#define NSTAGE 4
#define BNT 9              // 9 n-tiles of 8 -> 72 cols (64 data + ones + pad)

// smem layout (bytes): A raw fp32 4 stages | B fp16 4 stages | A fp16 2 bufs
#define ARAW_ST 2048       // floats per A stage (64 rows x 32)
#define BST_ST  1440       // u32 per B stage   (72 rows x 20)
#define AMM_ST  1280       // u32 per A buf     (64 rows x 20)
#define OFF_B   32768
#define OFF_AM  55808
#define DSMEM   66048

__device__ __half g_X2Th[72 * Kk];   // B^T fp16, K-major: row n = X2[k][n] over k
__device__ float  g_AGG[Nn * 64];    // (adj @ nx) / deg

__device__ __forceinline__ void cp16(void* s, const void* g) {
    uint32_t sa = (uint32_t)__cvta_generic_to_shared(s);
    asm volatile("cp.async.cg.shared.global [%0], [%1], 16;" :: "r"(sa), "l"(g));
}
__device__ __forceinline__ void cp_commit() { asm volatile("cp.async.commit_group;"); }
__device__ __forceinline__ void cp_wait2()  { asm volatile("cp.async.wait_group 2;"); }

// ---------------------------------------------------------------------------
// prep: transpose nx[16384,64] fp32 -> g_X2Th rows 0..63 (fp16, K-major)
// ---------------------------------------------------------------------------
__global__ __launch_bounds__(256) void prep_t(const float* __restrict__ nx) {
    __shared__ float t[64][65];
    const int kb = blockIdx.x * 64;
#pragma unroll
    for (int i = 0; i < 16; i++) {
        int id = threadIdx.x + 256 * i;
        int k = id >> 6, n = id & 63;
        t[k][n] = nx[(size_t)(kb + k) * 64 + n];
    }
    __syncthreads();
#pragma unroll
    for (int i = 0; i < 16; i++) {
        int id = threadIdx.x + 256 * i;
        int n = id >> 6, k = id & 63;
        g_X2Th[(size_t)n * Kk + kb + k] = __float2half_rn(t[k][n]);
    }
}
// rows 64..71: ones row (degree column) then zeros
__global__ __launch_bounds__(256) void prep_c() {
    int idx = blockIdx.x * 256 + threadIdx.x;          // 0 .. 8*16384-1
    g_X2Th[(size_t)64 * Kk + idx] = (idx < Kk) ? __float2half_rn(1.f)
                                               : __float2half_rn(0.f);
}

// ---------------------------------------------------------------------------
// main GEMM: 4-stage cp.async (A fp32 raw, B fp16), in-smem fp32->fp16 convert,
// mma.sync m16n8k16 fp16 with fp32 accumulators. Epilogue divides by the fused
// degree column (col 64) and writes g_AGG.
// ---------------------------------------------------------------------------
__global__ __launch_bounds__(128) void agg_gemm(const float* __restrict__ adj) {
    extern __shared__ char smem[];
    float*    Araw = (float*)smem;
    uint32_t* Bst  = (uint32_t*)(smem + OFF_B);
    uint32_t* Amm  = (uint32_t*)(smem + OFF_AM);

    const int tid  = threadIdx.x;
    const int lane = tid & 31;
    const int warp = tid >> 5;
    const int wm   = warp * 16;
    const int tid4 = lane & 3;
    const float* gA0 = adj + (size_t)blockIdx.x * BM * Kk;

    float c[BNT][4];
#pragma unroll
    for (int i = 0; i < BNT; i++) { c[i][0] = c[i][1] = c[i][2] = c[i][3] = 0.f; }

    auto load_stage = [&](int st, int kt) {
        const float* ga = gA0 + kt * KT;
        float* da = Araw + st * ARAW_ST;
#pragma unroll
        for (int i = 0; i < 4; i++) {                  // A: 64 rows x 128B
            int id = tid + 128 * i;
            int m = id >> 3, kg = id & 7;
            cp16(da + m * 32 + kg * 4, ga + (size_t)m * Kk + kg * 4);
        }
        const __half* gb = g_X2Th + kt * KT;
        uint32_t* db = Bst + st * BST_ST;
#pragma unroll
        for (int i = 0; i < 3; i++) {                  // B: 72 rows x 64B (fp16)
            int id = tid + 128 * i;
            if (id < 288) {
                int n = id >> 2, ch = id & 3;
                cp16(db + n * 20 + ch * 4, gb + (size_t)n * Kk + ch * 8);
            }
        }
    };

    for (int s = 0; s < NSTAGE - 1; s++) { load_stage(s, s); cp_commit(); }

    for (int kt = 0; kt < NKT; kt++) {
        const int st = kt & 3;
        cp_wait2();
        __syncthreads();

        // convert this warp's 16 A rows: fp32 raw -> fp16 pairs (stride 20 b32)
        {
            const float* src = Araw + st * ARAW_ST;
            uint32_t* dst = Amm + (kt & 1) * AMM_ST;
#pragma unroll
            for (int i = 0; i < 4; i++) {
                int row = wm + i * 4 + (lane >> 3);
                int c4  = (lane & 7) * 4;
                float4 v = *(const float4*)(src + row * 32 + c4);
                __half2 h0 = __floats2half2_rn(v.x, v.y);
                __half2 h1 = __floats2half2_rn(v.z, v.w);
                *(uint2*)(dst + row * 20 + (lane & 7) * 2) =
                    make_uint2(*(uint32_t*)&h0, *(uint32_t*)&h1);
            }
        }
        __syncwarp();

        const int nxt = kt + NSTAGE - 1;
        if (nxt < NKT) load_stage(nxt & 3, nxt);
        cp_commit();

        const uint32_t* Am = Amm + (kt & 1) * AMM_ST;
        const uint32_t* Bm = Bst + st * BST_ST;
        const int m0 = wm + (lane >> 2);
#pragma unroll
        for (int ks = 0; ks < 2; ks++) {
            const int kc = tid4 + ks * 8;
            uint32_t a0 = Am[m0 * 20 + kc];
            uint32_t a1 = Am[(m0 + 8) * 20 + kc];
            uint32_t a2 = Am[m0 * 20 + kc + 4];
            uint32_t a3 = Am[(m0 + 8) * 20 + kc + 4];
            const int nb = lane >> 2;
#pragma unroll
            for (int nt = 0; nt < BNT; nt++) {
                uint32_t b0 = Bm[(nt * 8 + nb) * 20 + kc];
                uint32_t b1 = Bm[(nt * 8 + nb) * 20 + kc + 4];
                asm volatile(
                    "mma.sync.aligned.m16n8k16.row.col.f32.f16.f16.f32 "
                    "{%0,%1,%2,%3}, {%4,%5,%6,%7}, {%8,%9}, {%0,%1,%2,%3};"
                    : "+f"(c[nt][0]), "+f"(c[nt][1]), "+f"(c[nt][2]), "+f"(c[nt][3])
                    : "r"(a0), "r"(a1), "r"(a2), "r"(a3), "r"(b0), "r"(b1));
            }
        }
    }

    // deg = column 64 = c[8][0]/c[8][2] on lanes with tid4==0; broadcast via shfl
    const float d0 = __shfl_sync(0xffffffff, c[8][0], lane & 28);
    const float d1 = __shfl_sync(0xffffffff, c[8][2], lane & 28);
    const float inv0 = 1.f / fmaxf(d0, 1.f);
    const float inv1 = 1.f / fmaxf(d1, 1.f);

    const int r0 = blockIdx.x * BM + wm + (lane >> 2);
#pragma unroll
    for (int nt = 0; nt < 8; nt++) {
        int col = nt * 8 + 2 * tid4;
        g_AGG[(size_t)r0 * 64 + col]           = c[nt][0] * inv0;
        g_AGG[(size_t)r0 * 64 + col + 1]       = c[nt][1] * inv0;
        g_AGG[(size_t)(r0 + 8) * 64 + col]     = c[nt][2] * inv1;
        g_AGG[(size_t)(r0 + 8) * 64 + col + 1] = c[nt][3] * inv1;
    }
}

// ---------------------------------------------------------------------------
// finalize: out[r,0:64] = self_x[r]@Ws + bs ; out[r,64:128] = AGG[r]@Wn + bn
// ---------------------------------------------------------------------------
__global__ __launch_bounds__(256) void finalize(
    const float* __restrict__ self_x, const float* __restrict__ Ws,
    const float* __restrict__ Wn, const float* __restrict__ bs,
    const float* __restrict__ bn, float* __restrict__ out)
{
    const int warp = threadIdx.x >> 5, lane = threadIdx.x & 31;
    const int r = blockIdx.x * 8 + warp;
    const bool selfside = lane < 16;
    const int c0 = selfside ? lane * 4 : (lane - 16) * 4;
    const float* src  = selfside ? (self_x + (size_t)r * 64) : (g_AGG + (size_t)r * 64);
    const float* W    = selfside ? Ws : Wn;
    const float* bias = selfside ? bs : bn;

    float4 acc = *(const float4*)(bias + c0);
#pragma unroll 8
    for (int k = 0; k < 64; k++) {
        float v = src[k];
        float4 w = *(const float4*)(W + k * 64 + c0);
        acc.x += v * w.x; acc.y += v * w.y; acc.z += v * w.z; acc.w += v * w.w;
    }
    *(float4*)(out + (size_t)r * 128 + lane * 4) = acc;
}

// ---------------------------------------------------------------------------
extern "C" void kernel_launch(void* const* d_in, const int* in_sizes, int n_in,
                              void* d_out, int out_size)
{
    const float* self_x     = (const float*)d_in[0];
    const float* neighbor_x = (const float*)d_in[1];
    const float* adj        = (const float*)d_in[2];
    const float* Ws         = (const float*)d_in[3];
    const float* Wn         = (const float*)d_in[4];
    const float* bs         = (const float*)d_in[5];
    const float* bn         = (const float*)d_in[6];
    float* out = (float*)d_out;

    cudaFuncSetAttribute(agg_gemm, cudaFuncAttributeMaxDynamicSharedMemorySize, DSMEM);

    prep_t<<<Kk / 64, 256>>>(neighbor_x);
    prep_c<<<(8 * Kk) / 256, 256>>>();
    agg_gemm<<<Nn / BM, 128, DSMEM>>>(adj);
    finalize<<<Nn / 8, 256>>>(self_x, Ws, Wn, bs, bn, out);
}